// round 4
// baseline (speedup 1.0000x reference)
#include <cuda_runtime.h>
#include <cuda_bf16.h>
#include <string.h>

#define MAXN   100000
#define HEADS  8
#define DIM    64
#define DKH    32
#define KNB    16
#define PC     (HEADS * DIM)   // 512 floats per row of P

typedef unsigned long long ull;

// Scratch (static __device__ — no allocation). 256B-aligned: both are read
// through 128-bit vector types, and __device__ float arrays otherwise carry
// no 16B alignment guarantee (wide-op misalignment is a HW trap, err715).
__device__ __align__(256) float g_M[HEADS * DIM * DIM]; // M[h][d][e] = sum_k WQ[h][d][k]*WK[h][e][k]
__device__ __align__(256) float g_P[(size_t)MAXN * PC]; // P[n][h*64+e] = sum_d Z[n][d]*M[h][d][e]
__device__ int g_idx_is64;

// Packed fp32x2 ops (Blackwell sm_103a)
#define FMA_F32X2(d_, a_, b_, c_) \
    asm("fma.rn.f32x2 %0, %1, %2, %3;" : "=l"(d_) : "l"(a_), "l"(b_), "l"(c_))
#define ADD_F32X2_(d_, a_, b_) \
    asm("add.rn.f32x2 %0, %1, %2;" : "=l"(d_) : "l"(a_), "l"(b_))

__device__ __forceinline__ ull dup_f32(float v) {
    unsigned u = __float_as_uint(v);
    return ((ull)u << 32) | (ull)u;
}
__device__ __forceinline__ float sum2(ull p) {
    float2 v; memcpy(&v, &p, 8);
    return v.x + v.y;
}

// ---------------------------------------------------------------------------
// Kernel 0: M[h] = WQ[h] @ WK[h]^T (8 blocks, one per head) + idx dtype probe
// (int64 values < 2^31 have zero high words; 32 random values in [0,100000)
// being all-zero as int32 is impossible in practice).
// ---------------------------------------------------------------------------
__global__ void __launch_bounds__(256)
gar_build_m(const float* __restrict__ WQ,
            const float* __restrict__ WK,
            const void*  __restrict__ idx_raw) {
    __shared__ float sq[DIM * DKH];
    __shared__ float sk[DIM * DKH];
    const int h = blockIdx.x;
    const int t = threadIdx.x;

    if (h == 0 && t == 0) {
        const int* p = (const int*)idx_raw;
        int any = 0;
        #pragma unroll
        for (int j = 0; j < 32; ++j) any |= p[2 * j + 1];
        g_idx_is64 = (any == 0) ? 1 : 0;
    }

    for (int i = t; i < DIM * DKH; i += 256) {
        sq[i] = WQ[h * DIM * DKH + i];
        sk[i] = WK[h * DIM * DKH + i];
    }
    __syncthreads();

    #pragma unroll
    for (int p = 0; p < 16; ++p) {
        const int o = (t << 4) + p;          // 0..4095
        const int d = o >> 6, e = o & 63;
        float s = 0.f;
        #pragma unroll
        for (int k = 0; k < DKH; ++k)
            s += sq[d * DKH + k] * sk[e * DKH + k];
        g_M[h * DIM * DIM + o] = s;
    }
}

// ---------------------------------------------------------------------------
// Kernel 1: P = Z @ Mcat  (GEMM M=N_rows, K=64, N=512) with packed f32x2.
// Thread t owns output columns (2t, 2t+1): W pair resident in 64 b64 regs.
// Z tile staged in static shared, PRE-DUPLICATED as (z,z) b64 pairs and read
// back as ulonglong2 (broadcast LDS.128) -> 2 FFMA2 per LDS wavefront,
// balancing the smem crossbar (~1 bcast wavefront/cyc/SM) against the FFMA2
// pipe (2 inst/cyc/SM). 256 FFMA2-issue cyc per row per SM at the floor.
// ---------------------------------------------------------------------------
#define ROWS1 64

__global__ void __launch_bounds__(256, 1)
gar_project(const float* __restrict__ Z, int N) {
    __shared__ __align__(16) ull zsh[ROWS1 * DIM];   // 32 KB duplicated pairs
    const int t  = threadIdx.x;
    const int c0 = 2 * t;                     // even -> same head block
    const int h  = c0 >> 6;
    const int e0 = c0 & 63;
    const int base = blockIdx.x * ROWS1;

    // W pair registers: wv[d] = (M[h][d][e0], M[h][d][e0+1])
    ull wv[DIM];
    {
        const float* mb = g_M + h * DIM * DIM + e0;
        #pragma unroll
        for (int d = 0; d < DIM; ++d) {
            ull v; memcpy(&v, mb + d * DIM, 8);   // 8B aligned (e0 even)
            wv[d] = v;
        }
    }

    // Stage duplicated Z tile: 1024 float4 loads -> 2048 ulonglong2 stores
    {
        ulonglong2* z2 = (ulonglong2*)zsh;
        #pragma unroll
        for (int it = 0; it < (ROWS1 * DIM / 4) / 256; ++it) {
            const int i  = it * 256 + t;          // float4 index
            const int r  = i >> 4;
            const int d4 = (i & 15) * 4;
            const int n  = base + r;
            float4 v = (n < N) ? *(const float4*)(Z + (size_t)n * DIM + d4)
                               : make_float4(0.f, 0.f, 0.f, 0.f);
            ulonglong2 p0, p1;
            p0.x = dup_f32(v.x); p0.y = dup_f32(v.y);
            p1.x = dup_f32(v.z); p1.y = dup_f32(v.w);
            z2[r * (DIM / 2) + (d4 >> 1)]     = p0;
            z2[r * (DIM / 2) + (d4 >> 1) + 1] = p1;
        }
    }
    __syncthreads();

    #pragma unroll 1
    for (int r = 0; r < ROWS1; ++r) {
        const ulonglong2* zr = (const ulonglong2*)(zsh + r * DIM);  // 32 vec
        ull a0 = 0, a1 = 0, a2 = 0, a3 = 0;   // 4 chains break the 4-cyc RAW
        #pragma unroll
        for (int q = 0; q < 32; q += 2) {
            ulonglong2 v0 = zr[q];
            ulonglong2 v1 = zr[q + 1];
            FMA_F32X2(a0, v0.x, wv[2 * q + 0], a0);
            FMA_F32X2(a1, v0.y, wv[2 * q + 1], a1);
            FMA_F32X2(a2, v1.x, wv[2 * q + 2], a2);
            FMA_F32X2(a3, v1.y, wv[2 * q + 3], a3);
        }
        ADD_F32X2_(a0, a0, a1);
        ADD_F32X2_(a2, a2, a3);
        ADD_F32X2_(a0, a0, a2);
        const int n = base + r;
        if (n < N) {
            float2 res; memcpy(&res, &a0, 8);
            *(float2*)(g_P + (size_t)n * PC + c0) = res;
        }
    }
}

// ---------------------------------------------------------------------------
// Kernel 2: attention. One warp per row i.
//   logits[h][j] = (P[i][h] . Z[idx[i][j]]) * scale - 0.5*(relu(f_i)+relu(f_j))
// Lane l: head h = l>>2, segment s = l&3 -> P floats [16l,16l+16), Z floats
// [16s,16s+16). Z gather = 256B rows from a 25.6 MB L2-resident table.
// Butterfly xor{1,2} completes each head dot; register softmax over K=16
// (replicated across the 4 s-lanes of a head); xor{4,8,16} sums the 8 heads;
// EMA blend + clamp.
// ---------------------------------------------------------------------------
#define MT 256

__global__ void __launch_bounds__(MT)
gar_attn(const float* __restrict__ Z,
         const float* __restrict__ f,
         const void*  __restrict__ idx_raw,
         const float* __restrict__ ema,
         float* __restrict__ out,
         int N) {
    const int i = blockIdx.x * (MT / 32) + (threadIdx.x >> 5);
    const int l = threadIdx.x & 31;
    if (i >= N) return;
    const unsigned FULL = 0xffffffffu;
    const int s = l & 3;

    // P segment: 16 floats = 8 packed pairs; warp reads one contiguous 2 KB row
    ull pp[8];
    {
        const ulonglong2* pb = (const ulonglong2*)(g_P + (size_t)i * PC + l * 16);
        #pragma unroll
        for (int q = 0; q < 4; ++q) {
            ulonglong2 v = pb[q];
            pp[2 * q] = v.x; pp[2 * q + 1] = v.y;
        }
    }

    const int is64 = g_idx_is64;
    long long nj_l = 0;
    float fn_l = 0.f;
    if (l < KNB) {
        if (is64) nj_l = ((const long long*)idx_raw)[(size_t)i * KNB + l];
        else      nj_l = (long long)((const int*)idx_raw)[(size_t)i * KNB + l];
        fn_l = fmaxf(f[nj_l], 0.f);
    }
    const float fi = fmaxf(f[i], 0.f);
    const float scale = 0.17677669529663687f;   // 1/sqrt(32)

    float lg[KNB];
    #pragma unroll
    for (int j = 0; j < KNB; ++j) {
        const long long nj = __shfl_sync(FULL, nj_l, j);
        const ulonglong2* zb = (const ulonglong2*)(Z + (size_t)nj * DIM + s * 16);
        ull a0 = 0, a1 = 0;
        #pragma unroll
        for (int q = 0; q < 4; ++q) {
            ulonglong2 zv = zb[q];
            FMA_F32X2(a0, zv.x, pp[2 * q], a0);
            FMA_F32X2(a1, zv.y, pp[2 * q + 1], a1);
        }
        ADD_F32X2_(a0, a0, a1);
        float p = sum2(a0);
        p += __shfl_xor_sync(FULL, p, 1);
        p += __shfl_xor_sync(FULL, p, 2);
        const float fj = __shfl_sync(FULL, fn_l, j);
        lg[j] = p * scale - 0.5f * (fi + fj);   // GAMMA=0.5, TAU=1
    }

    // Softmax over 16 neighbors (per head; replicated over the 4 s-lanes)
    float mx = lg[0];
    #pragma unroll
    for (int j = 1; j < KNB; ++j) mx = fmaxf(mx, lg[j]);
    float ssum = 0.f;
    #pragma unroll
    for (int j = 0; j < KNB; ++j) { float e = __expf(lg[j] - mx); lg[j] = e; ssum += e; }
    const float inv = 1.f / ssum;
    #pragma unroll
    for (int j = 0; j < KNB; ++j) lg[j] *= inv;

    // Sum over 8 heads: lanes {s, s+4, ..., s+28} hold distinct heads
    #pragma unroll
    for (int off = 4; off < 32; off <<= 1) {
        #pragma unroll
        for (int j = 0; j < KNB; ++j)
            lg[j] += __shfl_xor_sync(FULL, lg[j], off);
    }

    if (l < KNB) {
        float wv = lg[0];
        #pragma unroll
        for (int j = 1; j < KNB; ++j) if (l == j) wv = lg[j];
        const float wattn = wv * (1.f / HEADS);
        const float o = 0.9f * ema[(size_t)i * KNB + l] + 0.1f * wattn;
        out[(size_t)i * KNB + l] = fmaxf(o, 0.f);
    }
}

// ---------------------------------------------------------------------------
extern "C" void kernel_launch(void* const* d_in, const int* in_sizes, int n_in,
                              void* d_out, int out_size) {
    const float* Z   = (const float*)d_in[0];   // [N, 64]
    const float* f   = (const float*)d_in[1];   // [N]
    const float* WQ  = (const float*)d_in[2];   // [8, 64, 32]
    const float* WK  = (const float*)d_in[3];   // [8, 64, 32]
    const float* ema = (const float*)d_in[4];   // [N, 16]
    const void*  idx = (const void*)d_in[5];    // [N, 16] int64 or int32
    float* out = (float*)d_out;

    const int N = in_sizes[0] / DIM;

    gar_build_m<<<HEADS, 256>>>(WQ, WK, idx);
    gar_project<<<(N + ROWS1 - 1) / ROWS1, 256>>>(Z, N);

    const int rows_per_block = MT / 32;
    gar_attn<<<(N + rows_per_block - 1) / rows_per_block, MT>>>(Z, f, idx, ema, out, N);
}